// round 3
// baseline (speedup 1.0000x reference)
#include <cuda_runtime.h>
#include <math.h>
#include <cstdint>

#define BB   2
#define SS   2048
#define DD   1024
#define NH   16
#define DK   64
#define MTOT (BB * SS)        // 4096
#define NQKV (3 * DD)         // 3072

// Scratch (static device globals — no cudaMalloc anywhere)
__device__ float g_x[(size_t)MTOT * DD];        // 16 MB
__device__ float g_qkv[(size_t)MTOT * NQKV];    // 48 MB
__device__ float g_o[(size_t)MTOT * DD];        // 16 MB
__device__ float g_wqkvT[(size_t)NQKV * DD];    // 12 MB  (w_qkv transposed -> [N,K])
__device__ float g_woutT[(size_t)DD * DD];      //  4 MB  (w_out transposed -> [N,K])

// ---------------------------------------------------------------------------
// Helpers
// ---------------------------------------------------------------------------
__device__ __forceinline__ uint32_t f2tf32(float x) {
    uint32_t u;
    asm("cvt.rna.tf32.f32 %0, %1;" : "=r"(u) : "f"(x));
    return u;
}
__device__ __forceinline__ void mma_16n8k8_tf32(float* c, const uint32_t* a, const uint32_t* b) {
    asm volatile(
        "mma.sync.aligned.m16n8k8.row.col.f32.tf32.tf32.f32 "
        "{%0,%1,%2,%3}, {%4,%5,%6,%7}, {%8,%9}, {%0,%1,%2,%3};"
        : "+f"(c[0]), "+f"(c[1]), "+f"(c[2]), "+f"(c[3])
        : "r"(a[0]), "r"(a[1]), "r"(a[2]), "r"(a[3]), "r"(b[0]), "r"(b[1]));
}

// ---------------------------------------------------------------------------
// x = query + pos_emb
// ---------------------------------------------------------------------------
__global__ void add_pos_kernel(const float* __restrict__ q,
                               const float* __restrict__ pos,
                               float* __restrict__ x) {
    int i4 = (blockIdx.x * blockDim.x + threadIdx.x) * 4;
    float4 a = *(const float4*)(q + i4);
    float4 p = *(const float4*)(pos + (i4 & (SS * DD - 1)));
    a.x += p.x; a.y += p.y; a.z += p.z; a.w += p.w;
    *(float4*)(x + i4) = a;
}

// ---------------------------------------------------------------------------
// 32x32 tiled transpose: WT[n][k] = W[k][n]
// ---------------------------------------------------------------------------
__global__ void transpose_kernel(const float* __restrict__ W, float* __restrict__ WT,
                                 int K, int N) {
    __shared__ float t[32][33];
    int k0 = blockIdx.y * 32, n0 = blockIdx.x * 32;
    int tx = threadIdx.x, ty = threadIdx.y;
    for (int i = ty; i < 32; i += 8)
        t[i][tx] = W[(size_t)(k0 + i) * N + n0 + tx];
    __syncthreads();
    for (int i = ty; i < 32; i += 8)
        WT[(size_t)(n0 + i) * K + k0 + tx] = t[tx][i];
}

// ---------------------------------------------------------------------------
// tf32 mma.sync GEMM: C[M,N] = A[M,K] @ Bt[N,K]^T
// 128x128 CTA tile, BK=32, 256 threads (8 warps in 2x4), 64x32 warp tile.
// As[m][k], Bs[n][k] padded to stride 36 (conflict-free fragment LDS).
// ---------------------------------------------------------------------------
#define PADK 36

__global__ __launch_bounds__(256, 2)
void mma_gemm_kernel(int M, int N, int K,
                     const float* __restrict__ A,
                     const float* __restrict__ Bt,
                     float* __restrict__ C) {
    __shared__ uint32_t As[128 * PADK];
    __shared__ uint32_t Bs[128 * PADK];

    int tid = threadIdx.x;
    int wid = tid >> 5, lane = tid & 31;
    int g = lane >> 2;        // groupID 0..7
    int tg = lane & 3;        // threadInGroup 0..3
    int wr = wid >> 2;        // warp row 0..1  -> 64 rows
    int wc = wid & 3;         // warp col 0..3  -> 32 cols
    int row0 = blockIdx.y * 128, col0 = blockIdx.x * 128;

    float acc[4][4][4];       // [mi][ni][c0..c3]
#pragma unroll
    for (int mi = 0; mi < 4; mi++)
#pragma unroll
        for (int ni = 0; ni < 4; ni++)
#pragma unroll
            for (int c = 0; c < 4; c++) acc[mi][ni][c] = 0.f;

    // global load indexing: 1024 float4 per tile, 4 per thread
    int lrow = tid >> 3;            // 0..31 step -> row = lrow + i*32
    int lk   = (tid & 7) * 4;       // k offset 0,4,..28

    const float* Ag = A  + (size_t)row0 * K;
    const float* Bg = Bt + (size_t)col0 * K;

    for (int kt = 0; kt < K; kt += 32) {
#pragma unroll
        for (int i = 0; i < 4; i++) {
            int r = lrow + i * 32;
            float4 va = *(const float4*)(Ag + (size_t)r * K + kt + lk);
            uint4 ua = make_uint4(f2tf32(va.x), f2tf32(va.y), f2tf32(va.z), f2tf32(va.w));
            *(uint4*)(As + r * PADK + lk) = ua;
            float4 vb = *(const float4*)(Bg + (size_t)r * K + kt + lk);
            uint4 ub = make_uint4(f2tf32(vb.x), f2tf32(vb.y), f2tf32(vb.z), f2tf32(vb.w));
            *(uint4*)(Bs + r * PADK + lk) = ub;
        }
        __syncthreads();

#pragma unroll
        for (int ks = 0; ks < 4; ks++) {
            int k8 = ks * 8;
            uint32_t afr[4][4], bfr[4][2];
#pragma unroll
            for (int mi = 0; mi < 4; mi++) {
                int m = wr * 64 + mi * 16;
                afr[mi][0] = As[(m + g) * PADK + k8 + tg];
                afr[mi][1] = As[(m + g + 8) * PADK + k8 + tg];
                afr[mi][2] = As[(m + g) * PADK + k8 + tg + 4];
                afr[mi][3] = As[(m + g + 8) * PADK + k8 + tg + 4];
            }
#pragma unroll
            for (int ni = 0; ni < 4; ni++) {
                int n = wc * 32 + ni * 8;
                bfr[ni][0] = Bs[(n + g) * PADK + k8 + tg];
                bfr[ni][1] = Bs[(n + g) * PADK + k8 + tg + 4];
            }
#pragma unroll
            for (int mi = 0; mi < 4; mi++)
#pragma unroll
                for (int ni = 0; ni < 4; ni++)
                    mma_16n8k8_tf32(acc[mi][ni], afr[mi], bfr[ni]);
        }
        __syncthreads();
    }

    // epilogue: c0:(g, 2tg) c1:(g, 2tg+1) c2:(g+8, 2tg) c3:(g+8, 2tg+1)
#pragma unroll
    for (int mi = 0; mi < 4; mi++) {
#pragma unroll
        for (int ni = 0; ni < 4; ni++) {
            int r = row0 + wr * 64 + mi * 16 + g;
            int cc = col0 + wc * 32 + ni * 8 + tg * 2;
            *(float2*)(C + (size_t)r * N + cc) =
                make_float2(acc[mi][ni][0], acc[mi][ni][1]);
            *(float2*)(C + (size_t)(r + 8) * N + cc) =
                make_float2(acc[mi][ni][2], acc[mi][ni][3]);
        }
    }
}

// ---------------------------------------------------------------------------
// Flash attention (fp32) — unchanged
// ---------------------------------------------------------------------------
#define ATTN_SMEM_FLOATS (4096 + 4096 + 4096 + 4160 + 4096 + 64 + 64)
#define ATTN_SMEM_BYTES  (ATTN_SMEM_FLOATS * 4)

__global__ __launch_bounds__(256, 2)
void attn_kernel(const float* __restrict__ qkv, float* __restrict__ o) {
    extern __shared__ float sm[];
    float* Qs    = sm;
    float* Ks    = sm + 4096;
    float* Vs    = sm + 8192;
    float* Ss    = sm + 12288;
    float* Pt    = sm + 16448;
    float* alphs = sm + 20544;
    float* linv  = sm + 20608;

    int q0 = blockIdx.x * 64;
    int h  = blockIdx.y;
    int b  = blockIdx.z;
    int tid = threadIdx.x;
    int tx = tid & 15;
    int ty = tid >> 4;

    const float scale = 0.125f;

    const float* Qg = qkv + (size_t)(b * SS + q0) * NQKV + h * 3 * DK;
    for (int f = tid; f < 1024; f += 256) {
        int m = f >> 4;
        int d = (f & 15) * 4;
        float4 v = *(const float4*)(Qg + (size_t)m * NQKV + d);
        Qs[(d + 0) * 64 + m] = v.x * scale;
        Qs[(d + 1) * 64 + m] = v.y * scale;
        Qs[(d + 2) * 64 + m] = v.z * scale;
        Qs[(d + 3) * 64 + m] = v.w * scale;
    }

    float m_run = -INFINITY, l_run = 0.f;
    float o_acc[4][4];
#pragma unroll
    for (int i = 0; i < 4; i++)
#pragma unroll
        for (int j = 0; j < 4; j++) o_acc[i][j] = 0.f;

    __syncthreads();

    for (int t0 = 0; t0 < SS; t0 += 64) {
        const float* Kg = qkv + (size_t)(b * SS + t0) * NQKV + h * 3 * DK + DK;
        const float* Vg = Kg + DK;
        for (int f = tid; f < 1024; f += 256) {
            int n = f >> 4;
            int d = (f & 15) * 4;
            float4 kv = *(const float4*)(Kg + (size_t)n * NQKV + d);
            Ks[(d + 0) * 64 + n] = kv.x;
            Ks[(d + 1) * 64 + n] = kv.y;
            Ks[(d + 2) * 64 + n] = kv.z;
            Ks[(d + 3) * 64 + n] = kv.w;
            float4 vv = *(const float4*)(Vg + (size_t)n * NQKV + d);
            *(float4*)(Vs + n * 64 + d) = vv;
        }
        __syncthreads();

        float s_acc[4][4];
#pragma unroll
        for (int i = 0; i < 4; i++)
#pragma unroll
            for (int j = 0; j < 4; j++) s_acc[i][j] = 0.f;

#pragma unroll 8
        for (int d = 0; d < 64; d++) {
            float a[4], bb[4];
            *(float4*)a  = *(const float4*)(Qs + d * 64 + ty * 4);
            *(float4*)bb = *(const float4*)(Ks + d * 64 + tx * 4);
#pragma unroll
            for (int i = 0; i < 4; i++)
#pragma unroll
                for (int j = 0; j < 4; j++)
                    s_acc[i][j] += a[i] * bb[j];
        }
#pragma unroll
        for (int i = 0; i < 4; i++)
#pragma unroll
            for (int j = 0; j < 4; j++)
                Ss[(ty * 4 + i) * 65 + tx * 4 + j] = s_acc[i][j];
        __syncthreads();

        if (tid < 64) {
            int r = tid;
            float mt = m_run;
#pragma unroll 8
            for (int j = 0; j < 64; j++) mt = fmaxf(mt, Ss[r * 65 + j]);
            float al = __expf(m_run - mt);
            float sum = 0.f;
#pragma unroll 8
            for (int j = 0; j < 64; j++) {
                float p = __expf(Ss[r * 65 + j] - mt);
                Pt[j * 64 + r] = p;
                sum += p;
            }
            l_run = l_run * al + sum;
            m_run = mt;
            alphs[r] = al;
        }
        __syncthreads();

        float al[4];
#pragma unroll
        for (int i = 0; i < 4; i++) al[i] = alphs[ty * 4 + i];
#pragma unroll
        for (int i = 0; i < 4; i++)
#pragma unroll
            for (int j = 0; j < 4; j++) o_acc[i][j] *= al[i];

#pragma unroll 8
        for (int k = 0; k < 64; k++) {
            float a[4], bb[4];
            *(float4*)a  = *(const float4*)(Pt + k * 64 + ty * 4);
            *(float4*)bb = *(const float4*)(Vs + k * 64 + tx * 4);
#pragma unroll
            for (int i = 0; i < 4; i++)
#pragma unroll
                for (int j = 0; j < 4; j++)
                    o_acc[i][j] += a[i] * bb[j];
        }
        __syncthreads();
    }

    if (tid < 64) linv[tid] = 1.0f / l_run;
    __syncthreads();

#pragma unroll
    for (int i = 0; i < 4; i++) {
        float li = linv[ty * 4 + i];
        float4 v = make_float4(o_acc[i][0] * li, o_acc[i][1] * li,
                               o_acc[i][2] * li, o_acc[i][3] * li);
        *(float4*)(o + (size_t)(b * SS + q0 + ty * 4 + i) * DD + h * DK + tx * 4) = v;
    }
}

// ---------------------------------------------------------------------------
// Launch
// ---------------------------------------------------------------------------
extern "C" void kernel_launch(void* const* d_in, const int* in_sizes, int n_in,
                              void* d_out, int out_size) {
    const float* query = (const float*)d_in[0];
    const float* pos   = (const float*)d_in[1];
    const float* w_qkv = (const float*)d_in[2];
    const float* w_out = (const float*)d_in[3];
    float* out = (float*)d_out;

    float *xp, *qkvp, *op, *wqkvT, *woutT;
    cudaGetSymbolAddress((void**)&xp, g_x);
    cudaGetSymbolAddress((void**)&qkvp, g_qkv);
    cudaGetSymbolAddress((void**)&op, g_o);
    cudaGetSymbolAddress((void**)&wqkvT, g_wqkvT);
    cudaGetSymbolAddress((void**)&woutT, g_woutT);

    cudaFuncSetAttribute(attn_kernel,
                         cudaFuncAttributeMaxDynamicSharedMemorySize, ATTN_SMEM_BYTES);

    // 0) transpose weights to [N,K]
    transpose_kernel<<<dim3(NQKV / 32, DD / 32), dim3(32, 8)>>>(w_qkv, wqkvT, DD, NQKV);
    transpose_kernel<<<dim3(DD / 32, DD / 32), dim3(32, 8)>>>(w_out, woutT, DD, DD);

    // 1) x = query + pos
    add_pos_kernel<<<(MTOT * DD) / 4 / 256, 256>>>(query, pos, xp);

    // 2) qkv = x @ w_qkv  (tf32 mma.sync)
    mma_gemm_kernel<<<dim3(NQKV / 128, MTOT / 128), 256>>>(MTOT, NQKV, DD, xp, wqkvT, qkvp);

    // 3) flash attention -> o
    attn_kernel<<<dim3(SS / 64, NH, BB), 256, ATTN_SMEM_BYTES>>>(qkvp, op);

    // 4) out = o @ w_out  (tf32 mma.sync)
    mma_gemm_kernel<<<dim3(DD / 128, MTOT / 128), 256>>>(MTOT, DD, DD, op, woutT, out);
}